// round 12
// baseline (speedup 1.0000x reference)
#include <cuda_runtime.h>
#include <cstdint>

// ---------------- problem constants ----------------
#define C_     256
#define O_     256
#define HH     49
#define HW     2401            // 49*49
#define NPIX   76832           // 32*2401
#define KTOT   1792            // 256*7
#define BK     32              // K per chunk
#define NCHUNK 56              // 1792/32
#define BM     128             // Cout rows per CTA
#define BN     128             // pixels per CTA
#define PAD    36              // smem row stride in 4B words (32 + 4 pad)
#define TSZ    (BM * PAD)      // 4608 words per tile buffer
#define NPTILES 601            // ceil(76832/128)
#define SMEM_BYTES (4 * TSZ * 4)   // A0,B0,A1,B1 = 73728 B

// fp32 -> tf32, round-to-nearest. Truncation (what the MMA does to raw fp32
// bits) biases every product low by ~1e-3 relative; RN keeps error zero-mean.
static __device__ __forceinline__ uint32_t f2tf(float f) {
    uint32_t r;
    asm("cvt.rna.tf32.f32 %0, %1;" : "=r"(r) : "f"(f));
    return r;
}

__global__ void __launch_bounds__(256, 2)
hexconv_mma_kernel(const float* __restrict__ x,
                   const float* __restrict__ wgt,
                   const float* __restrict__ bias,
                   float* __restrict__ out)
{
    extern __shared__ uint32_t smem[];
    uint32_t* const A0 = smem;
    uint32_t* const B0 = smem + TSZ;
    uint32_t* const A1 = smem + 2 * TSZ;
    uint32_t* const B1 = smem + 3 * TSZ;

    const int tid   = threadIdx.x;
    const int wid   = tid >> 5;
    const int lid   = tid & 31;
    const int g     = lid >> 2;      // group id 0..7
    const int tig   = lid & 3;       // thread-in-group 0..3
    const int warp_m = wid & 3;      // 4 warps along M (32 rows each)
    const int warp_n = wid >> 2;     // 2 warps along N (64 cols each)
    const int coutbase = blockIdx.y * BM;

    // ---- per-thread gather setup: one pixel, half the K range ----
    const int pl    = tid & 127;     // pixel within tile (lanes consecutive -> coalesced)
    const int lo    = (tid >> 7) * 16;   // this thread covers kk in [lo, lo+16)
    const int p     = blockIdx.x * BN + pl;
    const bool pv   = (p < NPIX);
    const int pb    = pv ? (p / HW) : 0;
    const int prem  = pv ? (p - pb * HW) : 0;
    const int ph    = prem / HH;
    const int pw    = prem - ph * HH;
    const float* const xb = x + (size_t)pb * (C_ * HW);

    // 7 axial hex directions (dy,dx), k = c*7 + n
    int soff0, soff1, soff2, soff3, soff4, soff5, soff6;
    bool ok0, ok1, ok2, ok3, ok4, ok5, ok6;
#define MKDIR(i, DY, DX) { \
        int h2 = ph + (DY), w2 = pw + (DX); \
        ok##i = pv && ((unsigned)h2 < 49u) && ((unsigned)w2 < 49u) && \
                (h2 + w2 >= 24) && (h2 + w2 <= 72); \
        soff##i = h2 * HH + w2; }
    MKDIR(0, 0, 0) MKDIR(1, 1, 0) MKDIR(2, 0, 1) MKDIR(3, -1, 1)
    MKDIR(4, -1, 0) MKDIR(5, 0, -1) MKDIR(6, 1, -1)
#undef MKDIR

    float acc[2][8][4];
#pragma unroll
    for (int mt = 0; mt < 2; mt++)
#pragma unroll
        for (int nt = 0; nt < 8; nt++)
#pragma unroll
            for (int j = 0; j < 4; j++) acc[mt][nt][j] = 0.0f;

    // ---- fill one K-chunk (A: weights, B: gathered neighbors) ----
    auto fill_chunk = [&](int i, uint32_t* As, uint32_t* Bs) {
        const int k0 = i * BK;
        // A: 128 rows x 32 k, fp32 -> tf32, row stride PAD
#pragma unroll
        for (int e = 0; e < 4; e++) {
            const int elem = tid + e * 256;      // 0..1023 float4s
            const int row  = elem >> 3;
            const int q    = elem & 7;
            const float4 wv = __ldg(reinterpret_cast<const float4*>(
                wgt + (size_t)(coutbase + row) * KTOT + k0 + q * 4));
            uint32_t* d = As + row * PAD + q * 4;
            d[0] = f2tf(wv.x); d[1] = f2tf(wv.y);
            d[2] = f2tf(wv.z); d[3] = f2tf(wv.w);
        }
        // B: 128 pixels x 32 k; this thread writes kk in [lo, lo+16)
#define FILLDIR(i_, so_, ok_) { \
            int c  = (k0 + lo - (i_) + 6) / 7; \
            int kk = 7 * c + (i_) - k0; \
            for (; kk < lo + 16; c++, kk += 7) { \
                float v = (ok_) ? __ldg(xb + (so_) + c * HW) : 0.0f; \
                Bs[pl * PAD + kk] = f2tf(v); \
            } }
        FILLDIR(0, soff0, ok0) FILLDIR(1, soff1, ok1) FILLDIR(2, soff2, ok2)
        FILLDIR(3, soff3, ok3) FILLDIR(4, soff4, ok4) FILLDIR(5, soff5, ok5)
        FILLDIR(6, soff6, ok6)
#undef FILLDIR
    };

    // ---- one K-chunk of MMAs over the current buffers ----
    auto mma_chunk = [&](const uint32_t* As, const uint32_t* Bs) {
#pragma unroll
        for (int ks = 0; ks < 4; ks++) {
            const int k = ks * 8;
            uint32_t a[2][4];
#pragma unroll
            for (int mt = 0; mt < 2; mt++) {
                const uint32_t* ap = As + (warp_m * 32 + mt * 16 + g) * PAD + k + tig;
                a[mt][0] = ap[0];
                a[mt][1] = ap[8 * PAD];
                a[mt][2] = ap[4];
                a[mt][3] = ap[8 * PAD + 4];
            }
#pragma unroll
            for (int nt = 0; nt < 8; nt++) {
                const uint32_t* bp = Bs + (warp_n * 64 + nt * 8 + g) * PAD + k + tig;
                const uint32_t b0 = bp[0];
                const uint32_t b1 = bp[4];
#pragma unroll
                for (int mt = 0; mt < 2; mt++) {
                    float* c = acc[mt][nt];
                    asm volatile(
                        "mma.sync.aligned.m16n8k8.row.col.f32.tf32.tf32.f32 "
                        "{%0,%1,%2,%3}, {%4,%5,%6,%7}, {%8,%9}, {%0,%1,%2,%3};\n"
                        : "+f"(c[0]), "+f"(c[1]), "+f"(c[2]), "+f"(c[3])
                        : "r"(a[mt][0]), "r"(a[mt][1]), "r"(a[mt][2]), "r"(a[mt][3]),
                          "r"(b0), "r"(b1));
                }
            }
        }
    };

    // ---- double-buffered mainloop ----
    fill_chunk(0, A0, B0);
    __syncthreads();
    for (int i = 0; i < NCHUNK; i++) {
        const uint32_t* Ac = (i & 1) ? A1 : A0;
        const uint32_t* Bc = (i & 1) ? B1 : B0;
        uint32_t* An = (i & 1) ? A0 : A1;
        uint32_t* Bn = (i & 1) ? B0 : B1;
        if (i + 1 < NCHUNK) fill_chunk(i + 1, An, Bn);
        mma_chunk(Ac, Bc);
        __syncthreads();
    }

    // ---- epilogue: bias + hex output mask, straight to gmem ----
    const int ptile0 = blockIdx.x * BN;
#pragma unroll
    for (int mt = 0; mt < 2; mt++) {
#pragma unroll
        for (int half = 0; half < 2; half++) {
            const int o  = coutbase + warp_m * 32 + mt * 16 + half * 8 + g;
            const float bv = __ldg(bias + o);
#pragma unroll
            for (int nt = 0; nt < 8; nt++) {
#pragma unroll
                for (int j = 0; j < 2; j++) {
                    const int pp = ptile0 + warp_n * 64 + nt * 8 + tig * 2 + j;
                    if (pp < NPIX) {
                        const int b = pp / HW;
                        const int s = pp - b * HW;
                        const int h = s / HH;
                        const int w = s - h * HH;
                        float v = 0.0f;
                        if (h + w >= 24 && h + w <= 72)
                            v = acc[mt][nt][half * 2 + j] + bv;
                        out[(size_t)(b * O_ + o) * HW + s] = v;
                    }
                }
            }
        }
    }
}

extern "C" void kernel_launch(void* const* d_in, const int* in_sizes, int n_in,
                              void* d_out, int out_size)
{
    const float* x    = (const float*)d_in[0];   // [32,256,49,49] fp32
    const float* wgt  = (const float*)d_in[1];   // [256,256,7]    fp32
    const float* bias = (const float*)d_in[2];   // [256]          fp32
    float* out        = (float*)d_out;           // [32,256,49,49] fp32

    cudaFuncSetAttribute(hexconv_mma_kernel,
                         cudaFuncAttributeMaxDynamicSharedMemorySize, SMEM_BYTES);
    dim3 grid(NPTILES, 2);
    hexconv_mma_kernel<<<grid, 256, SMEM_BYTES>>>(x, wgt, bias, out);
}

// round 13
// speedup vs baseline: 1.5306x; 1.5306x over previous
#include <cuda_runtime.h>
#include <cstdint>

// ---------------- problem constants ----------------
#define C_     256
#define O_     256
#define HH     49
#define HW     2401            // 49*49
#define NPIX   76832           // 32*2401
#define KTOT   1792            // 256*7
#define BK     32              // K per chunk
#define NCHUNK 56              // 1792/32
#define BM     128             // Cout rows per CTA
#define BN     128             // pixels per CTA
#define NPTILES 601            // ceil(76832/128)

// B fragment smem: one fragment = 32 lanes x float2 {k, k+4}; stride 66 words
// (64 + 2 pad) makes both the scatter-STS in fill and the LDS.64 in the MMA
// loop conflict-free. 64 fragments = (ks 0..3) x (pixel-block nb 0..15).
#define BSTRIDE 66
#define BBUF    (64 * BSTRIDE)        // 4224 words = 16896 B
#define SMEM_WORDS (2 * BBUF)         // double buffered: 33792 B (static smem)

// A in tf32 fragment layout, precomputed once per launch into gmem (1.75 MB,
// L2-resident, reused by all CTAs). Index (uint4 units):
//   (((yt*56 + chunk)*4 + ks)*8 + mb)*32 + lid
// lane fragment = {A[r0][c], A[r0+8][c], A[r0][c+4], A[r0+8][c+4]},
//   r0 = yt*128 + mb*16 + (lid>>2), c = chunk*32 + ks*8 + (lid&3)
#define AFRAG_WORDS (2 * NCHUNK * 4 * 8 * 128)   // 458752 words
__device__ uint32_t g_afrag[AFRAG_WORDS];

// fp32 -> tf32, round-to-nearest (truncation would bias products low ~1e-3).
static __device__ __forceinline__ uint32_t f2tf(float f) {
    uint32_t r;
    asm("cvt.rna.tf32.f32 %0, %1;" : "=r"(r) : "f"(f));
    return r;
}

// ---------------- prep: weights -> tf32 fragment layout ----------------
__global__ void prep_afrag_kernel(const float* __restrict__ wgt)
{
    const int t = blockIdx.x * 256 + threadIdx.x;     // 114688 fragments
    if (t >= 2 * NCHUNK * 4 * 8 * 32) return;
    const int lid = t & 31;
    int r = t >> 5;
    const int mb = r & 7;      r >>= 3;
    const int ks = r & 3;      r >>= 2;
    const int chunk = r % NCHUNK;
    const int yt = r / NCHUNK;

    const int r0 = yt * 128 + mb * 16 + (lid >> 2);
    const int c  = chunk * BK + ks * 8 + (lid & 3);
    const float* w0 = wgt + (size_t)r0 * KTOT + c;
    const float* w1 = w0 + 8 * KTOT;
    uint4 v;
    v.x = f2tf(__ldg(w0));
    v.y = f2tf(__ldg(w1));
    v.z = f2tf(__ldg(w0 + 4));
    v.w = f2tf(__ldg(w1 + 4));
    reinterpret_cast<uint4*>(g_afrag)[t] = v;
}

// ---------------- main kernel ----------------
__global__ void __launch_bounds__(256, 2)
hexconv_mma_kernel(const float* __restrict__ x,
                   const float* __restrict__ bias,
                   float* __restrict__ out)
{
    __shared__ uint32_t smem[SMEM_WORDS];
    uint32_t* const B0 = smem;
    uint32_t* const B1 = smem + BBUF;

    const int tid   = threadIdx.x;
    const int wid   = tid >> 5;
    const int lid   = tid & 31;
    const int g     = lid >> 2;
    const int tig   = lid & 3;
    const int warp_m = wid & 3;      // 4 warps along M (32 rows each)
    const int warp_n = wid >> 2;     // 2 warps along N (64 pixels each)
    const int coutbase = blockIdx.y * BM;

    // ---- per-thread gather setup: one pixel, half the K range ----
    const int pl    = tid & 127;                 // pixel within tile
    const int lo    = (tid >> 7) * 16;           // kk range [lo, lo+16)
    const int p     = blockIdx.x * BN + pl;
    const bool pv   = (p < NPIX);
    const int pb    = pv ? (p / HW) : 0;
    const int prem  = pv ? (p - pb * HW) : 0;
    const int ph    = prem / HH;
    const int pw    = prem - ph * HH;
    const float* const xb = x + (size_t)pb * (C_ * HW);

    // B-fill scatter base for this thread's pixel:
    // word = ks*16*BSTRIDE + [nb*BSTRIDE + g*8] + tig*2 + half
    const int bbase = (pl >> 3) * BSTRIDE + (pl & 7) * 8;

    // 7 axial hex directions (dy,dx), k = c*7 + n
    int soff0, soff1, soff2, soff3, soff4, soff5, soff6;
    bool ok0, ok1, ok2, ok3, ok4, ok5, ok6;
#define MKDIR(i, DY, DX) { \
        int h2 = ph + (DY), w2 = pw + (DX); \
        ok##i = pv && ((unsigned)h2 < 49u) && ((unsigned)w2 < 49u) && \
                (h2 + w2 >= 24) && (h2 + w2 <= 72); \
        soff##i = h2 * HH + w2; }
    MKDIR(0, 0, 0) MKDIR(1, 1, 0) MKDIR(2, 0, 1) MKDIR(3, -1, 1)
    MKDIR(4, -1, 0) MKDIR(5, 0, -1) MKDIR(6, 1, -1)
#undef MKDIR

    float acc[2][8][4];
#pragma unroll
    for (int mt = 0; mt < 2; mt++)
#pragma unroll
        for (int nt = 0; nt < 8; nt++)
#pragma unroll
            for (int j = 0; j < 4; j++) acc[mt][nt][j] = 0.0f;

    // ---- fill one B K-chunk (gathered neighbors, fragment layout) ----
    auto fill_b = [&](int i, uint32_t* Bs) {
        const int k0 = i * BK;
#define FILLDIR(i_, so_, ok_) { \
            int c  = (k0 + lo - (i_) + 6) / 7; \
            int kk = 7 * c + (i_) - k0; \
            for (; kk < lo + 16; c++, kk += 7) { \
                float v = (ok_) ? __ldg(xb + (so_) + c * HW) : 0.0f; \
                const int w = (kk >> 3) * (16 * BSTRIDE) + bbase + \
                              ((kk & 3) << 1) + ((kk >> 2) & 1); \
                Bs[w] = f2tf(v); \
            } }
        FILLDIR(0, soff0, ok0) FILLDIR(1, soff1, ok1) FILLDIR(2, soff2, ok2)
        FILLDIR(3, soff3, ok3) FILLDIR(4, soff4, ok4) FILLDIR(5, soff5, ok5)
        FILLDIR(6, soff6, ok6)
#undef FILLDIR
    };

    // ---- one K-chunk of MMAs: A from gmem fragments, B from smem ----
    auto mma_chunk = [&](int i, const uint32_t* Bs) {
        const uint4* ap = reinterpret_cast<const uint4*>(g_afrag) +
                          (size_t)((blockIdx.y * NCHUNK + i) * 4) * 8 * 32;
        uint4 a[4][2];
#pragma unroll
        for (int ks = 0; ks < 4; ks++)
#pragma unroll
            for (int mt = 0; mt < 2; mt++)
                a[ks][mt] = __ldg(ap + (ks * 8 + warp_m * 2 + mt) * 32 + lid);

#pragma unroll
        for (int ks = 0; ks < 4; ks++) {
#pragma unroll
            for (int nt = 0; nt < 8; nt++) {
                const uint2 b = *reinterpret_cast<const uint2*>(
                    Bs + (ks * 16 + warp_n * 8 + nt) * BSTRIDE + lid * 2);
#pragma unroll
                for (int mt = 0; mt < 2; mt++) {
                    float* c = acc[mt][nt];
                    asm volatile(
                        "mma.sync.aligned.m16n8k8.row.col.f32.tf32.tf32.f32 "
                        "{%0,%1,%2,%3}, {%4,%5,%6,%7}, {%8,%9}, {%0,%1,%2,%3};\n"
                        : "+f"(c[0]), "+f"(c[1]), "+f"(c[2]), "+f"(c[3])
                        : "r"(a[ks][mt].x), "r"(a[ks][mt].y),
                          "r"(a[ks][mt].z), "r"(a[ks][mt].w),
                          "r"(b.x), "r"(b.y));
                }
            }
        }
    };

    // ---- double-buffered mainloop ----
    fill_b(0, B0);
    __syncthreads();
    for (int i = 0; i < NCHUNK; i++) {
        const uint32_t* Bc = (i & 1) ? B1 : B0;
        uint32_t*       Bn = (i & 1) ? B0 : B1;
        if (i + 1 < NCHUNK) fill_b(i + 1, Bn);
        mma_chunk(i, Bc);
        __syncthreads();
    }

    // ---- epilogue: bias + hex output mask, straight to gmem ----
    const int ptile0 = blockIdx.x * BN;
#pragma unroll
    for (int mt = 0; mt < 2; mt++) {
#pragma unroll
        for (int half = 0; half < 2; half++) {
            const int o  = coutbase + warp_m * 32 + mt * 16 + half * 8 + g;
            const float bv = __ldg(bias + o);
#pragma unroll
            for (int nt = 0; nt < 8; nt++) {
#pragma unroll
                for (int j = 0; j < 2; j++) {
                    const int pp = ptile0 + warp_n * 64 + nt * 8 + tig * 2 + j;
                    if (pp < NPIX) {
                        const int b = pp / HW;
                        const int s = pp - b * HW;
                        const int h = s / HH;
                        const int w = s - h * HH;
                        float v = 0.0f;
                        if (h + w >= 24 && h + w <= 72)
                            v = acc[mt][nt][half * 2 + j] + bv;
                        out[(size_t)(b * O_ + o) * HW + s] = v;
                    }
                }
            }
        }
    }
}

extern "C" void kernel_launch(void* const* d_in, const int* in_sizes, int n_in,
                              void* d_out, int out_size)
{
    const float* x    = (const float*)d_in[0];   // [32,256,49,49] fp32
    const float* wgt  = (const float*)d_in[1];   // [256,256,7]    fp32
    const float* bias = (const float*)d_in[2];   // [256]          fp32
    float* out        = (float*)d_out;           // [32,256,49,49] fp32

    prep_afrag_kernel<<<448, 256>>>(wgt);
    dim3 grid(NPTILES, 2);
    hexconv_mma_kernel<<<grid, 256>>>(x, bias, out);
}

// round 14
// speedup vs baseline: 2.2976x; 1.5011x over previous
#include <cuda_runtime.h>
#include <cstdint>

// ---------------- problem constants ----------------
#define C_     256
#define O_     256
#define HH     49
#define HW     2401            // 49*49
#define NPIX   76832           // 32*2401
#define KTOT   1792            // 256*7
#define BK     32              // K per chunk
#define NCHUNK 56              // 1792/32
#define BM     128             // Cout rows per CTA
#define BN     128             // pixels per CTA
#define NPTILES 601            // ceil(76832/128)

// ---- B im2col matrix, tf32 bits, fragment layout (uint2 per lane) ----
// uint2 index: (((ptile*56 + chunk)*4 + ks)*16 + nb)*32 + lid
//   pixel = ptile*128 + nb*8 + (lid>>2)
//   b.x: k = chunk*32 + ks*8 + (lid&3)      b.y: k = +4
#define BFRAG_U2 ((size_t)NPTILES * NCHUNK * 4 * 16 * 32)   // 68.9M uint2 = 551MB
__device__ uint2 g_bfrag[BFRAG_U2];

// ---- A in tf32 fragment layout (uint4 per lane), 1.75MB, L2-resident ----
// uint4 index: (((yt*56 + chunk)*4 + ks)*8 + mb)*32 + lid
#define AFRAG_WORDS (2 * NCHUNK * 4 * 8 * 128)
__device__ uint32_t g_afrag[AFRAG_WORDS];

// per-chunk smem B buffer: 4 ks x 16 nb fragments x 64 words = 4096 words
#define BBUF 4096
#define SMEM_WORDS (2 * BBUF)      // 32KB static, double buffered

// fp32 -> tf32, round-to-nearest (truncation would bias products low ~1e-3).
static __device__ __forceinline__ uint32_t f2tf(float f) {
    uint32_t r;
    asm("cvt.rna.tf32.f32 %0, %1;" : "=r"(r) : "f"(f));
    return r;
}

// hex directions packed: (d+1) nibbles, n=0..6
// dy: {0,1,0,-1,-1,0,1} -> +1: {1,2,1,0,0,1,2}
// dx: {0,0,1,1,0,-1,-1} -> +1: {1,1,2,2,1,0,0}
#define DYP 0x2100121u
#define DXP 0x0012211u

// ---------------- prep: weights -> tf32 A-fragment layout ----------------
__global__ void prep_afrag_kernel(const float* __restrict__ wgt)
{
    const int t = blockIdx.x * 256 + threadIdx.x;     // 114688 lane-fragments
    if (t >= 2 * NCHUNK * 4 * 8 * 32) return;
    const int lid = t & 31;
    int r = t >> 5;
    const int mb = r & 7;      r >>= 3;
    const int ks = r & 3;      r >>= 2;
    const int chunk = r % NCHUNK;
    const int yt = r / NCHUNK;

    const int r0 = yt * 128 + mb * 16 + (lid >> 2);
    const int c  = chunk * BK + ks * 8 + (lid & 3);
    const float* w0 = wgt + (size_t)r0 * KTOT + c;
    const float* w1 = w0 + 8 * KTOT;
    uint4 v;
    v.x = f2tf(__ldg(w0));
    v.y = f2tf(__ldg(w1));
    v.z = f2tf(__ldg(w0 + 4));
    v.w = f2tf(__ldg(w1 + 4));
    reinterpret_cast<uint4*>(g_afrag)[t] = v;
}

// ---------------- im2col: gathered hex neighbors -> B fragments ----------------
// one thread = (ptile, chunk, nb, lid), produces 4 uint2 (ks = 0..3)
#define I2C_THREADS (NPTILES * NCHUNK * 16 * 32)      // 17,231,872
__global__ void __launch_bounds__(256)
im2col_kernel(const float* __restrict__ x)
{
    const int t = blockIdx.x * 256 + threadIdx.x;
    if (t >= I2C_THREADS) return;
    const int lid = t & 31;
    const int nb  = (t >> 5) & 15;
    const int r   = t >> 9;
    const int chunk = r % NCHUNK;
    const int ptile = r / NCHUNK;

    const int p  = ptile * 128 + nb * 8 + (lid >> 2);
    const bool pv = (p < NPIX);
    const int pb   = pv ? (p / HW) : 0;
    const int prem = pv ? (p - pb * HW) : 0;
    const int ph = prem / HH;
    const int pw = prem - ph * HH;
    const float* const xb = x + (size_t)pb * (C_ * HW);

    const int kbase = chunk * BK + (lid & 3);
    uint2* dst = g_bfrag + ((size_t)(ptile * NCHUNK + chunk) * 4 * 16 + nb) * 32 + lid;

#pragma unroll
    for (int ks = 0; ks < 4; ks++) {
        float v[2];
#pragma unroll
        for (int half = 0; half < 2; half++) {
            const int k = kbase + ks * 8 + half * 4;
            const int c = k / 7;
            const int n = k - c * 7;
            const int h2 = ph + (int)((DYP >> (4 * n)) & 15) - 1;
            const int w2 = pw + (int)((DXP >> (4 * n)) & 15) - 1;
            const bool ok = pv && ((unsigned)h2 < 49u) && ((unsigned)w2 < 49u) &&
                            (h2 + w2 >= 24) && (h2 + w2 <= 72);
            v[half] = ok ? __ldg(xb + c * HW + h2 * HH + w2) : 0.0f;
        }
        uint2 o;
        o.x = f2tf(v[0]);
        o.y = f2tf(v[1]);
        dst[ks * 16 * 32] = o;
    }
}

// ---------------- main GEMM ----------------
__global__ void __launch_bounds__(256, 2)
hexconv_mma_kernel(const float* __restrict__ bias,
                   float* __restrict__ out)
{
    __shared__ uint32_t smem[SMEM_WORDS];
    uint32_t* const B0 = smem;
    uint32_t* const B1 = smem + BBUF;

    const int tid   = threadIdx.x;
    const int wid   = tid >> 5;
    const int lid   = tid & 31;
    const int g     = lid >> 2;
    const int tig   = lid & 3;
    const int warp_m = wid & 3;      // 4 warps along M (32 rows each)
    const int warp_n = wid >> 2;     // 2 warps along N (64 pixels each)
    const int coutbase = blockIdx.y * BM;

    float acc[2][8][4];
#pragma unroll
    for (int mt = 0; mt < 2; mt++)
#pragma unroll
        for (int nt = 0; nt < 8; nt++)
#pragma unroll
            for (int j = 0; j < 4; j++) acc[mt][nt][j] = 0.0f;

    // ---- B fill: straight coalesced copy of one 16KB fragment chunk ----
    const uint4* const bsrc0 = reinterpret_cast<const uint4*>(g_bfrag) +
                               (size_t)blockIdx.x * NCHUNK * 1024;
    auto fill_b = [&](int i, uint32_t* Bs) {
        const uint4* src = bsrc0 + (size_t)i * 1024;
        uint4* dst = reinterpret_cast<uint4*>(Bs);
#pragma unroll
        for (int e = 0; e < 4; e++) {
            const int idx = tid + e * 256;
            dst[idx] = __ldg(src + idx);
        }
    };

    // ---- one K-chunk of MMAs: A from gmem fragments, B from smem ----
    auto mma_chunk = [&](int i, const uint32_t* Bs) {
        const uint4* ap = reinterpret_cast<const uint4*>(g_afrag) +
                          (size_t)((blockIdx.y * NCHUNK + i) * 4) * 8 * 32;
        uint4 a[4][2];
#pragma unroll
        for (int ks = 0; ks < 4; ks++)
#pragma unroll
            for (int mt = 0; mt < 2; mt++)
                a[ks][mt] = __ldg(ap + (ks * 8 + warp_m * 2 + mt) * 32 + lid);

#pragma unroll
        for (int ks = 0; ks < 4; ks++) {
#pragma unroll
            for (int nt = 0; nt < 8; nt++) {
                const uint2 b = *reinterpret_cast<const uint2*>(
                    Bs + (ks * 16 + warp_n * 8 + nt) * 64 + lid * 2);
#pragma unroll
                for (int mt = 0; mt < 2; mt++) {
                    float* c = acc[mt][nt];
                    asm volatile(
                        "mma.sync.aligned.m16n8k8.row.col.f32.tf32.tf32.f32 "
                        "{%0,%1,%2,%3}, {%4,%5,%6,%7}, {%8,%9}, {%0,%1,%2,%3};\n"
                        : "+f"(c[0]), "+f"(c[1]), "+f"(c[2]), "+f"(c[3])
                        : "r"(a[ks][mt].x), "r"(a[ks][mt].y),
                          "r"(a[ks][mt].z), "r"(a[ks][mt].w),
                          "r"(b.x), "r"(b.y));
                }
            }
        }
    };

    // ---- double-buffered mainloop ----
    fill_b(0, B0);
    __syncthreads();
    for (int i = 0; i < NCHUNK; i++) {
        const uint32_t* Bc = (i & 1) ? B1 : B0;
        uint32_t*       Bn = (i & 1) ? B0 : B1;
        if (i + 1 < NCHUNK) fill_b(i + 1, Bn);
        mma_chunk(i, Bc);
        __syncthreads();
    }

    // ---- epilogue: bias + hex output mask, straight to gmem ----
    const int ptile0 = blockIdx.x * BN;
#pragma unroll
    for (int mt = 0; mt < 2; mt++) {
#pragma unroll
        for (int half = 0; half < 2; half++) {
            const int o  = coutbase + warp_m * 32 + mt * 16 + half * 8 + g;
            const float bv = __ldg(bias + o);
#pragma unroll
            for (int nt = 0; nt < 8; nt++) {
#pragma unroll
                for (int j = 0; j < 2; j++) {
                    const int pp = ptile0 + warp_n * 64 + nt * 8 + tig * 2 + j;
                    if (pp < NPIX) {
                        const int b = pp / HW;
                        const int s = pp - b * HW;
                        const int h = s / HH;
                        const int w = s - h * HH;
                        float v = 0.0f;
                        if (h + w >= 24 && h + w <= 72)
                            v = acc[mt][nt][half * 2 + j] + bv;
                        out[(size_t)(b * O_ + o) * HW + s] = v;
                    }
                }
            }
        }
    }
}

extern "C" void kernel_launch(void* const* d_in, const int* in_sizes, int n_in,
                              void* d_out, int out_size)
{
    const float* x    = (const float*)d_in[0];   // [32,256,49,49] fp32
    const float* wgt  = (const float*)d_in[1];   // [256,256,7]    fp32
    const float* bias = (const float*)d_in[2];   // [256]          fp32
    float* out        = (float*)d_out;           // [32,256,49,49] fp32

    prep_afrag_kernel<<<448, 256>>>(wgt);
    im2col_kernel<<<(I2C_THREADS + 255) / 256, 256>>>(x);
    dim3 grid(NPTILES, 2);
    hexconv_mma_kernel<<<grid, 256>>>(bias, out);
}

// round 15
// speedup vs baseline: 2.8817x; 1.2542x over previous
#include <cuda_runtime.h>
#include <cstdint>

// ---------------- problem constants ----------------
#define C_     256
#define O_     256
#define HH     49
#define HW     2401            // 49*49
#define KTOT   1792            // 256*7
#define BK     32              // K per chunk
#define NCHUNK 56              // 1792/32
#define BM     128             // Cout rows per CTA
#define BN     128             // pixels per CTA

// hex-valid pixels only (h+w in [24,72]): 1801 per image, 32 images
#define NVROW   1801
#define NVALID  57632          // 32*1801
#define NVTILES 451            // ceil(57632/128)

// ---- valid-pixel map: r in [0,1801) -> s = h*49+w (u32 for simplicity) ----
__device__ uint32_t g_vmap[NVROW];

// ---- B im2col matrix (compacted N), tf32 bits, fragment layout ----
// uint2 index: (((ptile*56 + chunk)*4 + ks)*16 + nb)*32 + lid
//   vp = ptile*128 + nb*8 + (lid>>2)   (valid-pixel index)
//   b.x: k = chunk*32 + ks*8 + (lid&3)   b.y: k = +4
#define BFRAG_U2 ((size_t)NVTILES * NCHUNK * 4 * 16 * 32)   // 413.8 MB
__device__ uint2 g_bfrag[BFRAG_U2];

// ---- A in tf32 fragment layout (uint4 per lane), 1.75MB, L2-resident ----
#define AFRAG_WORDS (2 * NCHUNK * 4 * 8 * 128)
__device__ uint32_t g_afrag[AFRAG_WORDS];

// per-chunk smem B buffer: 4 ks x 16 nb fragments x 64 words = 4096 words
#define BBUF 4096
#define SMEM_WORDS (2 * BBUF)      // 32KB static, double buffered

// fp32 -> tf32, round-to-nearest (truncation would bias products low ~1e-3).
static __device__ __forceinline__ uint32_t f2tf(float f) {
    uint32_t r;
    asm("cvt.rna.tf32.f32 %0, %1;" : "=r"(r) : "f"(f));
    return r;
}

// hex directions packed: (d+1) nibbles, n=0..6
// dy: {0,1,0,-1,-1,0,1}  dx: {0,0,1,1,0,-1,-1}
#define DYP 0x2100121u
#define DXP 0x0012211u

// ---------------- prep: valid-pixel map ----------------
__global__ void prep_vmap_kernel()
{
    const int h = threadIdx.x;
    if (h >= HH) return;
    // base(h) = sum_{i<h} (49 - |24-i|)
    int base;
    if (h <= 25) base = 25 * h + h * (h - 1) / 2;
    else {
        const int m = h - 25;                 // rows 25..h-1, counts 48,47,...
        base = 925 + m * 48 - m * (m - 1) / 2;
    }
    const int wmin = (h < 24) ? (24 - h) : 0;
    const int wmax = (h > 24) ? (72 - h) : 48;
    for (int w = wmin; w <= wmax; w++)
        g_vmap[base + (w - wmin)] = (uint32_t)(h * HH + w);
}

// ---------------- prep: zero output ----------------
__global__ void zero_out_kernel(float* __restrict__ out, int n4)
{
    const int t = blockIdx.x * 256 + threadIdx.x;
    if (t < n4)
        reinterpret_cast<uint4*>(out)[t] = make_uint4(0u, 0u, 0u, 0u);
}

// ---------------- prep: weights -> tf32 A-fragment layout ----------------
__global__ void prep_afrag_kernel(const float* __restrict__ wgt)
{
    const int t = blockIdx.x * 256 + threadIdx.x;     // 114688 lane-fragments
    if (t >= 2 * NCHUNK * 4 * 8 * 32) return;
    const int lid = t & 31;
    int r = t >> 5;
    const int mb = r & 7;      r >>= 3;
    const int ks = r & 3;      r >>= 2;
    const int chunk = r % NCHUNK;
    const int yt = r / NCHUNK;

    const int r0 = yt * 128 + mb * 16 + (lid >> 2);
    const int c  = chunk * BK + ks * 8 + (lid & 3);
    const float* w0 = wgt + (size_t)r0 * KTOT + c;
    const float* w1 = w0 + 8 * KTOT;
    uint4 v;
    v.x = f2tf(__ldg(w0));
    v.y = f2tf(__ldg(w1));
    v.z = f2tf(__ldg(w0 + 4));
    v.w = f2tf(__ldg(w1 + 4));
    reinterpret_cast<uint4*>(g_afrag)[t] = v;
}

// ---------------- im2col (compacted): hex gather -> B fragments ----------------
// one thread = (ptile, chunk, nb, lid), produces 4 uint2 (ks = 0..3)
#define I2C_THREADS (NVTILES * NCHUNK * 16 * 32)      // 12,930,048
__global__ void __launch_bounds__(256)
im2col_kernel(const float* __restrict__ x)
{
    const int t = blockIdx.x * 256 + threadIdx.x;
    if (t >= I2C_THREADS) return;
    const int lid = t & 31;
    const int nb  = (t >> 5) & 15;
    const int r   = t >> 9;
    const int chunk = r % NCHUNK;
    const int ptile = r / NCHUNK;

    const int vp = ptile * 128 + nb * 8 + (lid >> 2);
    const bool pv = (vp < NVALID);
    const int pb = pv ? (vp / NVROW) : 0;
    const int pr = pv ? (vp - pb * NVROW) : 0;
    const int s  = (int)__ldg(g_vmap + pr);
    const int ph = s / HH;
    const int pw = s - ph * HH;
    const float* const xb = x + (size_t)pb * (C_ * HW);

    const int kbase = chunk * BK + (lid & 3);
    uint2* dst = g_bfrag + ((size_t)(ptile * NCHUNK + chunk) * 4 * 16 + nb) * 32 + lid;

#pragma unroll
    for (int ks = 0; ks < 4; ks++) {
        float v[2];
#pragma unroll
        for (int half = 0; half < 2; half++) {
            const int k = kbase + ks * 8 + half * 4;
            const int c = k / 7;
            const int n = k - c * 7;
            const int h2 = ph + (int)((DYP >> (4 * n)) & 15) - 1;
            const int w2 = pw + (int)((DXP >> (4 * n)) & 15) - 1;
            const bool ok = pv && ((unsigned)h2 < 49u) && ((unsigned)w2 < 49u) &&
                            (h2 + w2 >= 24) && (h2 + w2 <= 72);
            v[half] = ok ? __ldg(xb + c * HW + h2 * HH + w2) : 0.0f;
        }
        uint2 o;
        o.x = f2tf(v[0]);
        o.y = f2tf(v[1]);
        dst[ks * 16 * 32] = o;
    }
}

// ---------------- main GEMM ----------------
__global__ void __launch_bounds__(256, 2)
hexconv_mma_kernel(const float* __restrict__ bias,
                   float* __restrict__ out)
{
    __shared__ uint32_t smem[SMEM_WORDS];
    uint32_t* const B0 = smem;
    uint32_t* const B1 = smem + BBUF;

    const int tid   = threadIdx.x;
    const int wid   = tid >> 5;
    const int lid   = tid & 31;
    const int g     = lid >> 2;
    const int tig   = lid & 3;
    const int warp_m = wid & 3;      // 4 warps along M (32 rows each)
    const int warp_n = wid >> 2;     // 2 warps along N (64 pixels each)
    const int coutbase = blockIdx.y * BM;

    float acc[2][8][4];
#pragma unroll
    for (int mt = 0; mt < 2; mt++)
#pragma unroll
        for (int nt = 0; nt < 8; nt++)
#pragma unroll
            for (int j = 0; j < 4; j++) acc[mt][nt][j] = 0.0f;

    // ---- B fill: straight coalesced copy of one 16KB fragment chunk ----
    const uint4* const bsrc0 = reinterpret_cast<const uint4*>(g_bfrag) +
                               (size_t)blockIdx.x * NCHUNK * 1024;
    auto fill_b = [&](int i, uint32_t* Bs) {
        const uint4* src = bsrc0 + (size_t)i * 1024;
        uint4* dst = reinterpret_cast<uint4*>(Bs);
#pragma unroll
        for (int e = 0; e < 4; e++) {
            const int idx = tid + e * 256;
            dst[idx] = __ldg(src + idx);
        }
    };

    // ---- one K-chunk of MMAs: A from gmem fragments, B from smem ----
    auto mma_chunk = [&](int i, const uint32_t* Bs) {
        const uint4* ap = reinterpret_cast<const uint4*>(g_afrag) +
                          (size_t)((blockIdx.y * NCHUNK + i) * 4) * 8 * 32;
        uint4 a[4][2];
#pragma unroll
        for (int ks = 0; ks < 4; ks++)
#pragma unroll
            for (int mt = 0; mt < 2; mt++)
                a[ks][mt] = __ldg(ap + (ks * 8 + warp_m * 2 + mt) * 32 + lid);

#pragma unroll
        for (int ks = 0; ks < 4; ks++) {
#pragma unroll
            for (int nt = 0; nt < 8; nt++) {
                const uint2 b = *reinterpret_cast<const uint2*>(
                    Bs + (ks * 16 + warp_n * 8 + nt) * 64 + lid * 2);
#pragma unroll
                for (int mt = 0; mt < 2; mt++) {
                    float* c = acc[mt][nt];
                    asm volatile(
                        "mma.sync.aligned.m16n8k8.row.col.f32.tf32.tf32.f32 "
                        "{%0,%1,%2,%3}, {%4,%5,%6,%7}, {%8,%9}, {%0,%1,%2,%3};\n"
                        : "+f"(c[0]), "+f"(c[1]), "+f"(c[2]), "+f"(c[3])
                        : "r"(a[ks][mt].x), "r"(a[ks][mt].y),
                          "r"(a[ks][mt].z), "r"(a[ks][mt].w),
                          "r"(b.x), "r"(b.y));
                }
            }
        }
    };

    // ---- double-buffered mainloop ----
    fill_b(0, B0);
    __syncthreads();
    for (int i = 0; i < NCHUNK; i++) {
        const uint32_t* Bc = (i & 1) ? B1 : B0;
        uint32_t*       Bn = (i & 1) ? B0 : B1;
        if (i + 1 < NCHUNK) fill_b(i + 1, Bn);
        mma_chunk(i, Bc);
        __syncthreads();
    }

    // ---- epilogue: bias add, scatter via vmap (masked pixels stay zero) ----
    const int vtile0 = blockIdx.x * BN;
#pragma unroll
    for (int mt = 0; mt < 2; mt++) {
#pragma unroll
        for (int half = 0; half < 2; half++) {
            const int o  = coutbase + warp_m * 32 + mt * 16 + half * 8 + g;
            const float bv = __ldg(bias + o);
#pragma unroll
            for (int nt = 0; nt < 8; nt++) {
#pragma unroll
                for (int j = 0; j < 2; j++) {
                    const int vp = vtile0 + warp_n * 64 + nt * 8 + tig * 2 + j;
                    if (vp < NVALID) {
                        const int b = vp / NVROW;
                        const int r = vp - b * NVROW;
                        const int s = (int)__ldg(g_vmap + r);
                        out[(size_t)(b * O_ + o) * HW + s] =
                            acc[mt][nt][half * 2 + j] + bv;
                    }
                }
            }
        }
    }
}

extern "C" void kernel_launch(void* const* d_in, const int* in_sizes, int n_in,
                              void* d_out, int out_size)
{
    const float* x    = (const float*)d_in[0];   // [32,256,49,49] fp32
    const float* wgt  = (const float*)d_in[1];   // [256,256,7]    fp32
    const float* bias = (const float*)d_in[2];   // [256]          fp32
    float* out        = (float*)d_out;           // [32,256,49,49] fp32

    const int n4 = out_size / 4;                 // out_size divisible by 4
    prep_vmap_kernel<<<1, 64>>>();
    zero_out_kernel<<<(n4 + 255) / 256, 256>>>(out, n4);
    prep_afrag_kernel<<<448, 256>>>(wgt);
    im2col_kernel<<<(I2C_THREADS + 255) / 256, 256>>>(x);
    dim3 grid(NVTILES, 2);
    hexconv_mma_kernel<<<grid, 256>>>(bias, out);
}